// round 5
// baseline (speedup 1.0000x reference)
#include <cuda_runtime.h>

// (B,C,D,H,W) = (4,8,16,256,256), k=3, stride=1, pad=1
#define BC   32
#define DD   16
#define HH   256
#define WW   256
#define HW   (HH*WW)
#define CHV  (DD*HW)

#define TH    16              // tile height
#define TWID  32              // tile width (1 px / thread)
#define ROWS  (TH+2)          // 18
#define COLS  (TWID+2)        // 34
#define TS    (ROWS*COLS)     // 612
#define NT    (TH*TWID)       // 512

__global__ void __launch_bounds__(NT, 3)
softargmax_kernel(const float* __restrict__ x, float* __restrict__ out)
{
    const int bc = blockIdx.z;
    const int h0 = blockIdx.y * TH;
    const int w0 = blockIdx.x * TWID;
    const int tid = threadIdx.x;
    const int tx = tid & 31;
    const int ty = tid >> 5;

    // double-buffered (e, e*x) slice tiles
    __shared__ __align__(16) float2 tile[2][TS];

    const float* __restrict__ xc = x + (size_t)bc * CHV;

    // two load slots cover TS=612 (slot0: all 512 threads, slot1: tid<100)
    int off0, off1;
    bool pr0, pr1, in1;
    {
        int r = tid / COLS, c = tid % COLS;
        int hh = h0 + r - 1, ww = w0 + c - 1;
        pr0 = (hh >= 0) && (hh < HH) && (ww >= 0) && (ww < WW);
        off0 = pr0 ? hh * WW + ww : 0;
        int i = tid + NT;
        in1 = (i < TS);
        r = i / COLS; c = i % COLS;
        hh = h0 + r - 1; ww = w0 + c - 1;
        pr1 = in1 && (hh >= 0) && (hh < HH) && (ww >= 0) && (ww < WW);
        off1 = pr1 ? hh * WW + ww : 0;
    }

    float rv0 = pr0 ? __ldg(xc + off0) : 0.f;
    float rv1 = pr1 ? __ldg(xc + off1) : 0.f;

    #define PUBLISH(BUF)                                                      \
        do {                                                                  \
            float e0 = pr0 ? __expf(rv0) : 0.f;                               \
            tile[BUF][tid] = make_float2(e0, e0 * rv0);                       \
            if (in1) {                                                        \
                float e1 = pr1 ? __expf(rv1) : 0.f;                           \
                tile[BUF][tid + NT] = make_float2(e1, e1 * rv1);              \
            }                                                                 \
        } while (0)

    // s[0]=sum, s[1]=xnum, s[2]=ynum, s[3]=vnum (one pixel)
    #define ACCUM(s, BUF)                                                     \
        _Pragma("unroll")                                                     \
        for (int r = 0; r < 3; r++) {                                         \
            const float2 A = tile[BUF][(ty + r) * COLS + tx];                 \
            const float2 Bv = tile[BUF][(ty + r) * COLS + tx + 1];            \
            const float2 Cv = tile[BUF][(ty + r) * COLS + tx + 2];            \
            float rs = A.x + Bv.x + Cv.x;                                     \
            (s)[0] += rs;                                                     \
            (s)[1] += Cv.x - A.x;                                             \
            if (r == 0) (s)[2] -= rs;                                         \
            if (r == 2) (s)[2] += rs;                                         \
            (s)[3] += A.y + Bv.y + Cv.y;                                      \
        }

    float p[4] = {0.f, 0.f, 0.f, 0.f};
    float c[4] = {0.f, 0.f, 0.f, 0.f};
    float n[4];

    // prologue: slice 0
    PUBLISH(0);
    rv0 = pr0 ? __ldg(xc + HW + off0) : 0.f;   // prefetch slice 1
    rv1 = pr1 ? __ldg(xc + HW + off1) : 0.f;
    __syncthreads();
    ACCUM(c, 0);

    const float hf = (float)(h0 + ty);
    const float wf = (float)(w0 + tx);
    const size_t pixbase = (size_t)(h0 + ty) * WW + (w0 + tx);
    float* pcoord = out + (size_t)bc * 3 * CHV + pixbase;                 // z-plane
    float* pval   = out + (size_t)BC * 3 * CHV + (size_t)bc * CHV + pixbase;

    #pragma unroll
    for (int d = 0; d < DD; d++) {
        n[0] = n[1] = n[2] = n[3] = 0.f;

        if (d + 1 < DD) {
            const int buf = (d + 1) & 1;
            PUBLISH(buf);                       // slice d+1
            if (d + 2 < DD) {                   // prefetch slice d+2
                const float* xs2 = xc + (size_t)(d + 2) * HW;
                rv0 = pr0 ? __ldg(xs2 + off0) : 0.f;
                rv1 = pr1 ? __ldg(xs2 + off1) : 0.f;
            }
            __syncthreads();                    // one barrier per slice
            ACCUM(n, buf);
        }

        const float inv = __fdividef(1.0f, p[0] + c[0] + n[0] + 1e-8f);

        __stcs(pcoord,            (float)d + (n[0] - p[0]) * inv);
        __stcs(pcoord + CHV,      wf + (p[1] + c[1] + n[1]) * inv);
        __stcs(pcoord + 2 * CHV,  hf + (p[2] + c[2] + n[2]) * inv);
        __stcs(pval,              (p[3] + c[3] + n[3]) * inv);

        pcoord += HW;
        pval   += HW;

        p[0] = c[0]; p[1] = c[1]; p[2] = c[2]; p[3] = c[3];
        c[0] = n[0]; c[1] = n[1]; c[2] = n[2]; c[3] = n[3];
    }
}

extern "C" void kernel_launch(void* const* d_in, const int* in_sizes, int n_in,
                              void* d_out, int out_size) {
    const float* x = (const float*)d_in[0];
    float* out = (float*)d_out;
    softargmax_kernel<<<dim3(WW / TWID, HH / TH, BC), NT>>>(x, out);
}